// round 15
// baseline (speedup 1.0000x reference)
#include <cuda_runtime.h>
#include <cuda_fp16.h>
#include <math.h>
#include <stdint.h>

// ---------------------------------------------------------------------------
// Problem constants
// ---------------------------------------------------------------------------
#define B_   64
#define S_   512
#define F_   512
#define HS_  1024
#define G3_  3072
#define M_   (B_ * S_)

// Persistent config: 32 gate-grouped n-tiles (96 cols) x 4 K-splits = 128 blocks
#define NTILES 32
#define KSPLIT 4
#define NBLK_P (NTILES * KSPLIT)     // 128
#define NTC    96                    // cols per tile (3 gates x 32 cc)
#define KPER   256                   // k per block
#define KC     32                    // k chunk
#define NCH    (KPER / KC)           // 8
#define NTHR   384                   // 12 warps

// smem (recurrence): W 8 chunks x 6KB = 49152; A 8 chunks x 4KB
#define SMW_CH   6144
#define SMA_OFF  49152
#define SMA_CH   4096
#define SMEM_TOT 81920

// ---------------------------------------------------------------------------
// Device scratch
// ---------------------------------------------------------------------------
__device__ float g_gx[(size_t)M_ * G3_];
__device__ float g_ghp[2][KSPLIT][B_ * G3_];        // partials, dbl-buf by t&1
__device__ __half g_hh16[4][B_ * HS_];              // h fp16 (4-deep)
__device__ __half g_wt16[(size_t)G3_ * HS_];        // W_hh^T fp16, PERMUTED rows
__device__ __half g_wi16[(size_t)G3_ * F_];         // W_ih^T fp16 [3072][512]
__device__ __half g_x16[(size_t)M_ * F_];           // x fp16 [32768][512]

// Monotone counters, prezeroed each launch. tdone 16B-aligned for v4 polls.
__device__ unsigned g_pdone[S_ * NTILES];                       // ->4
__device__ __align__(16) unsigned g_tdone[(S_ + 1) * NTILES];   // ->4

// ---------------------------------------------------------------------------
// PTX helpers (compute_80-level — target is compute_103 non-'a')
// ---------------------------------------------------------------------------
__device__ __forceinline__ uint32_t s2u(const void* p) {
    uint32_t r;
    asm("{ .reg .u64 t; cvta.to.shared.u64 t, %1; cvt.u32.u64 %0, t; }"
        : "=r"(r) : "l"(p));
    return r;
}
__device__ __forceinline__ void cpasync16(uint32_t dst, const void* src) {
    asm volatile("cp.async.cg.shared.global [%0], [%1], 16;"
                 :: "r"(dst), "l"(src));
}
__device__ __forceinline__ void ldsm4(uint32_t* r, uint32_t addr) {
    asm volatile("ldmatrix.sync.aligned.m8n8.x4.shared.b16 {%0,%1,%2,%3}, [%4];"
                 : "=r"(r[0]), "=r"(r[1]), "=r"(r[2]), "=r"(r[3]) : "r"(addr));
}
__device__ __forceinline__ void mma_f16(float* c, const uint32_t* a,
                                        const uint32_t* b) {
    asm volatile(
        "mma.sync.aligned.m16n8k16.row.col.f32.f16.f16.f32 "
        "{%0,%1,%2,%3}, {%4,%5,%6,%7}, {%8,%9}, {%0,%1,%2,%3};"
        : "+f"(c[0]), "+f"(c[1]), "+f"(c[2]), "+f"(c[3])
        : "r"(a[0]), "r"(a[1]), "r"(a[2]), "r"(a[3]), "r"(b[0]), "r"(b[1]));
}
__device__ __forceinline__ float ldcg(const float* p) {
    float v;
    asm volatile("ld.global.cg.f32 %0, [%1];" : "=f"(v) : "l"(p));
    return v;
}
// Fire-and-forget global add (REDG, no return value on the critical hop)
__device__ __forceinline__ void redadd(unsigned* p, unsigned v) {
    asm volatile("red.global.add.u32 [%0], %1;" :: "l"(p), "r"(v) : "memory");
}
// Fast activations (error: few ulp — negligible vs budget)
__device__ __forceinline__ float fsig(float x) {
    return __fdividef(1.0f, 1.0f + __expf(-x));
}
__device__ __forceinline__ float ftanh(float x) {
    return 1.0f - __fdividef(2.0f, __expf(2.0f * x) + 1.0f);
}
// 16B-granule swizzle for 64B rows: conflict-free 8-row ldmatrix phases.
__device__ __forceinline__ uint32_t swz(int r, int q) {
    return (uint32_t)(r * 64 + ((q ^ ((r >> 1) & 3)) << 4));
}
#define WAITG(n) asm volatile("cp.async.wait_group %0;" :: "n"(n))

// ---------------------------------------------------------------------------
// Fused prep kernel: x->fp16, Wih^T fp16, Whh^T fp16 (gate-grouped perm),
// h0 zero, counters zero. Grid 16384 x 1024 (covers the largest array).
// ---------------------------------------------------------------------------
__global__ void prep_all_kernel(const float* __restrict__ x,
                                const float* __restrict__ whh,
                                const float* __restrict__ wih) {
    size_t i = (size_t)blockIdx.x * blockDim.x + threadIdx.x;

    // x: 16,777,216 elems (full grid)
    g_x16[i] = __float2half(x[i]);

    // W_hh^T permuted: 3,145,728 elems
    if (i < (size_t)G3_ * HS_) {
        int k = (int)(i / G3_), n = (int)(i % G3_);
        int gate = n / HS_, cc = n % HS_;
        int n_new = (cc >> 5) * NTC + gate * 32 + (cc & 31);
        g_wt16[(size_t)n_new * HS_ + k] = __float2half(whh[i]);
    }
    // W_ih^T: 1,572,864 elems
    if (i < (size_t)G3_ * F_) {
        int k = (int)(i / G3_), n = (int)(i % G3_);
        g_wi16[(size_t)n * F_ + k] = __float2half(wih[i]);
    }
    // h0 zero: 65,536
    if (i < (size_t)(B_ * HS_)) g_hh16[0][i] = __float2half(0.0f);
    // counters
    if (i < (size_t)(S_ * NTILES))       g_pdone[i] = 0u;
    if (i < (size_t)((S_ + 1) * NTILES)) g_tdone[i] = 0u;
}

// ---------------------------------------------------------------------------
// Phase 1 GEMM (validated R14, unchanged): gx = x16 @ Wih16^T (+bias).
// ---------------------------------------------------------------------------
__global__ void __launch_bounds__(128) mma_gemm16_kernel(
    const __half* __restrict__ A, const __half* __restrict__ Bw,
    float* __restrict__ out, const float* __restrict__ bias, int K)
{
    __shared__ __align__(16) uint8_t smem_raw[2][12288];  // A 4KB + B 8KB
    const int tid = threadIdx.x, lid = tid & 31, wid = tid >> 5;
    const int wm = wid & 1, wn = wid >> 1;
    const int m0 = blockIdx.y * 64, n0 = blockIdx.x * 128;
    const uint32_t sm0 = s2u(smem_raw[0]), sm1 = s2u(smem_raw[1]);

    float acc[2][8][4];
#pragma unroll
    for (int i = 0; i < 2; i++)
#pragma unroll
        for (int j = 0; j < 8; j++)
#pragma unroll
            for (int v = 0; v < 4; v++) acc[i][j][v] = 0.0f;

    const int NC = K >> 5;
    auto load_chunk = [&](uint32_t sb, int k0) {
#pragma unroll
        for (int i = 0; i < 2; i++) {
            int cid = tid + i * 128;
            int r = cid >> 2, q = cid & 3;
            cpasync16(sb + swz(r, q), A + (size_t)(m0 + r) * K + k0 + q * 8);
        }
#pragma unroll
        for (int i = 0; i < 4; i++) {
            int cid = tid + i * 128;
            int r = cid >> 2, q = cid & 3;
            cpasync16(sb + 4096 + swz(r, q), Bw + (size_t)(n0 + r) * K + k0 + q * 8);
        }
        asm volatile("cp.async.commit_group;");
    };

    load_chunk(sm0, 0);
    for (int c = 0; c < NC; c++) {
        if (c + 1 < NC) {
            load_chunk(((c + 1) & 1) ? sm1 : sm0, (c + 1) * KC);
            asm volatile("cp.async.wait_group 1;");
        } else {
            asm volatile("cp.async.wait_group 0;");
        }
        __syncthreads();
        const uint32_t sb = (c & 1) ? sm1 : sm0;
#pragma unroll
        for (int kk = 0; kk < 2; kk++) {
            const int qq = kk * 2 + (lid >> 4);
            uint32_t afr[2][4];
#pragma unroll
            for (int i = 0; i < 2; i++) {
                int r = wm * 32 + i * 16 + (lid & 15);
                ldsm4(afr[i], sb + swz(r, qq));
            }
            uint32_t bfr[8][2];
#pragma unroll
            for (int jj = 0; jj < 4; jj++) {
                int r = wn * 64 + jj * 16 + (lid & 15);
                uint32_t t4[4];
                ldsm4(t4, sb + 4096 + swz(r, qq));
                bfr[2 * jj][0] = t4[0]; bfr[2 * jj][1] = t4[2];
                bfr[2 * jj + 1][0] = t4[1]; bfr[2 * jj + 1][1] = t4[3];
            }
#pragma unroll
            for (int i = 0; i < 2; i++)
#pragma unroll
                for (int j = 0; j < 8; j++)
                    mma_f16(acc[i][j], afr[i], bfr[j]);
        }
        __syncthreads();
    }
#pragma unroll
    for (int i = 0; i < 2; i++) {
        int m = m0 + wm * 32 + 16 * i + (lid >> 2);
#pragma unroll
        for (int j = 0; j < 8; j++) {
            int n = n0 + wn * 64 + 8 * j + 2 * (lid & 3);
            float b0 = bias[n], b1 = bias[n + 1];
            *(float2*)(out + (size_t)m * G3_ + n) =
                make_float2(acc[i][j][0] + b0, acc[i][j][1] + b1);
            *(float2*)(out + (size_t)(m + 8) * G3_ + n) =
                make_float2(acc[i][j][2] + b0, acc[i][j][3] + b1);
        }
    }
}

// ---------------------------------------------------------------------------
// Persistent recurrence (numerics FROZEN from R14). Changes this round:
//   - split-half producer wait: poll producers 0-3, issue chunks 0-3,
//     poll 4-7, issue 4-7 (earlier A-load start under skew)
//   - red.global.add for the h publish (no-return)
// ---------------------------------------------------------------------------
__global__ void __launch_bounds__(NTHR) gru_persist_kernel(
    float* __restrict__ out, float* __restrict__ lastdst)
{
    extern __shared__ __align__(16) uint8_t smem[];
    const uint32_t wbase = s2u(smem);
    const uint32_t abase = wbase + SMA_OFF;

    const int tid = threadIdx.x, lid = tid & 31, wid = tid >> 5;
    const int wm = wid & 1;            // 0..1
    const int wn = wid >> 1;           // 0..5
    const int tile = blockIdx.x % NTILES;     // 0..31
    const int kh   = blockIdx.x / NTILES;     // 0..3
    const int n0   = tile * NTC;
    const int kbase = kh * KPER;

    // ---- one-time: W16 tile load (3072 granules, 8/thread) ----
#pragma unroll
    for (int i = 0; i < 8; i++) {
        int gid = tid + i * NTHR;
        int c   = gid / 384;           // chunk 0..7
        int g   = gid % 384;
        int r   = g >> 2, q = g & 3;   // row 0..95
        cpasync16(wbase + c * SMW_CH + swz(r, q),
                  g_wt16 + (size_t)(n0 + r) * HS_ + kbase + c * KC + q * 8);
    }
    asm volatile("cp.async.commit_group;");
    asm volatile("cp.async.wait_group 0;");
    __syncthreads();

    const int b0 = kh * 16;            // pointwise batch slice
    float hreg[2] = {0.0f, 0.0f};      // register-carried h for own slice

    for (int t = 0; t < S_; t++) {
        const __half* __restrict__ Ah = g_hh16[t & 3] + kbase;

        // ---- half 0: wait producers 8kh..8kh+3, then issue chunks 0-3 ----
        if (t > 0) {
            if (tid == 0) {
                const unsigned* p = &g_tdone[t * NTILES + 8 * kh];
                while (true) {
                    unsigned a0, a1, a2, a3;
                    asm volatile("ld.volatile.global.v4.u32 {%0,%1,%2,%3}, [%4];"
                                 : "=r"(a0), "=r"(a1), "=r"(a2), "=r"(a3)
                                 : "l"(p));
                    if ((a0 & a1 & a2 & a3) == 4u && (a0 | a1 | a2 | a3) == 4u)
                        break;
                }
            }
            __syncthreads();
        }
#pragma unroll
        for (int c = 0; c < 4; c++) {
            if (tid < 256) {
                int r = tid >> 2, q = tid & 3;
                cpasync16(abase + c * SMA_CH + swz(r, q),
                          Ah + (size_t)r * HS_ + c * KC + q * 8);
            }
            asm volatile("cp.async.commit_group;");
        }

        // ---- half 1: wait producers 8kh+4..8kh+7, then issue chunks 4-7 ----
        if (t > 0) {
            if (tid == 0) {
                const unsigned* p = &g_tdone[t * NTILES + 8 * kh + 4];
                while (true) {
                    unsigned a0, a1, a2, a3;
                    asm volatile("ld.volatile.global.v4.u32 {%0,%1,%2,%3}, [%4];"
                                 : "=r"(a0), "=r"(a1), "=r"(a2), "=r"(a3)
                                 : "l"(p));
                    if ((a0 & a1 & a2 & a3) == 4u && (a0 | a1 | a2 | a3) == 4u)
                        break;
                }
            }
            __syncthreads();
        }
#pragma unroll
        for (int c = 4; c < 8; c++) {
            if (tid < 256) {
                int r = tid >> 2, q = tid & 3;
                cpasync16(abase + c * SMA_CH + swz(r, q),
                          Ah + (size_t)r * HS_ + c * KC + q * 8);
            }
            asm volatile("cp.async.commit_group;");
        }

        // ---- load this step's gx values into registers (off-chain) ----
        float gxv[2][3];
#pragma unroll
        for (int p = 0; p < 2; p++) {
            int e = tid + p * NTHR;
            if (e < 512) {
                int b  = b0 + (e >> 5);
                int cc = tile * 32 + (e & 31);
                const float* gxp = g_gx + ((size_t)b * S_ + t) * G3_;
                gxv[p][0] = gxp[cc];
                gxv[p][1] = gxp[HS_ + cc];
                gxv[p][2] = gxp[2 * HS_ + cc];
            } else {
                gxv[p][0] = gxv[p][1] = gxv[p][2] = 0.0f;
            }
        }

        float acc[2][2][4];
#pragma unroll
        for (int i = 0; i < 2; i++)
#pragma unroll
            for (int j = 0; j < 2; j++)
#pragma unroll
                for (int v = 0; v < 4; v++) acc[i][j][v] = 0.0f;

        // ---- chunk compute body: 1-term fp16 ----
        auto comp = [&](int c) {
            const uint32_t sbA = abase + c * SMA_CH;
            const uint32_t sbW = wbase + c * SMW_CH;
#pragma unroll
            for (int kk = 0; kk < 2; kk++) {
                const int qq = kk * 2 + (lid >> 4);
                uint32_t afr[2][4];
#pragma unroll
                for (int i = 0; i < 2; i++) {
                    int r = wm * 32 + i * 16 + (lid & 15);
                    ldsm4(afr[i], sbA + swz(r, qq));
                }
                uint32_t bfr[2][2];
                {
                    int r = wn * 16 + (lid & 15);
                    uint32_t t4[4];
                    ldsm4(t4, sbW + swz(r, qq));
                    bfr[0][0] = t4[0]; bfr[0][1] = t4[2];
                    bfr[1][0] = t4[1]; bfr[1][1] = t4[3];
                }
#pragma unroll
                for (int i = 0; i < 2; i++)
#pragma unroll
                    for (int j = 0; j < 2; j++)
                        mma_f16(acc[i][j], afr[i], bfr[j]);
            }
        };

        // ---- quarter-granularity pipeline ----
        WAITG(6); __syncthreads(); comp(0); comp(1);
        WAITG(4); __syncthreads(); comp(2); comp(3);
        WAITG(2); __syncthreads(); comp(4); comp(5);
        WAITG(0); __syncthreads(); comp(6); comp(7);

        // ---- store partial gh tile (parity buffer) ----
        float* __restrict__ ghdst = g_ghp[t & 1][kh];
#pragma unroll
        for (int i = 0; i < 2; i++) {
            int m = wm * 32 + 16 * i + (lid >> 2);
#pragma unroll
            for (int j = 0; j < 2; j++) {
                int nc = n0 + wn * 16 + 8 * j + 2 * (lid & 3);
                *(float2*)(ghdst + (size_t)m * G3_ + nc) =
                    make_float2(acc[i][j][0], acc[i][j][1]);
                *(float2*)(ghdst + (size_t)(m + 8) * G3_ + nc) =
                    make_float2(acc[i][j][2], acc[i][j][3]);
            }
        }

        // ---- tile-local 4-way sync ----
        __threadfence();
        __syncthreads();
        if (tid == 0) {
            unsigned old = atomicAdd(&g_pdone[t * NTILES + tile], 1u);
            if (old != 3u) {
                while (*((volatile unsigned*)&g_pdone[t * NTILES + tile]) != 4u) { }
            }
        }
        __syncthreads();

        // ---- pointwise for own slice: 16 b x 32 cc = 512 elems ----
        const int tp = t & 1;
        const int o  = (t + 1) & 3;
        float hn_sv[2];
        int   hidx_sv[2];
        int   b_sv[2];
        int   cc_sv[2];
#pragma unroll
        for (int p = 0; p < 2; p++) {
            hn_sv[p] = 0.0f; hidx_sv[p] = -1; b_sv[p] = 0; cc_sv[p] = 0;
            int e = tid + p * NTHR;
            if (e < 512) {
                int b  = b0 + (e >> 5);
                int ccl = e & 31;
                int cc  = tile * 32 + ccl;
                size_t base = (size_t)b * G3_ + n0 + ccl;
                float ghz = ldcg(g_ghp[tp][0] + base)      + ldcg(g_ghp[tp][1] + base)
                          + ldcg(g_ghp[tp][2] + base)      + ldcg(g_ghp[tp][3] + base);
                float ghr = ldcg(g_ghp[tp][0] + base + 32) + ldcg(g_ghp[tp][1] + base + 32)
                          + ldcg(g_ghp[tp][2] + base + 32) + ldcg(g_ghp[tp][3] + base + 32);
                float ghe = ldcg(g_ghp[tp][0] + base + 64) + ldcg(g_ghp[tp][1] + base + 64)
                          + ldcg(g_ghp[tp][2] + base + 64) + ldcg(g_ghp[tp][3] + base + 64);
                float z   = fsig(gxv[p][0] + ghz);
                float r   = fsig(gxv[p][1] + ghr);
                float eta = ftanh(gxv[p][2] + r * ftanh(ghe));
                float hn  = z * hreg[p] + (1.0f - z) * eta;
                hreg[p] = hn;
                int hidx = b * HS_ + cc;
                // consumers need ONLY hh16 -> store it now
                g_hh16[o][hidx] = __float2half(hn);
                hn_sv[p] = hn; hidx_sv[p] = hidx; b_sv[p] = b; cc_sv[p] = cc;
            }
        }

        // ---- publish h(t+1) cols for this tile (EARLY, no-return red) ----
        __threadfence();
        __syncthreads();
        if (tid == 0) redadd(&g_tdone[(t + 1) * NTILES + tile], 1u);

        // ---- off-critical-path writes: out, lastdst ----
#pragma unroll
        for (int p = 0; p < 2; p++) {
            if (hidx_sv[p] >= 0) {
                out[((size_t)b_sv[p] * S_ + t) * HS_ + cc_sv[p]] = hn_sv[p];
                if (lastdst && t == S_ - 1) lastdst[hidx_sv[p]] = hn_sv[p];
            }
        }
    }
}

// ---------------------------------------------------------------------------
// Host launch — 3 graph nodes.
// ---------------------------------------------------------------------------
extern "C" void kernel_launch(void* const* d_in, const int* in_sizes, int n_in,
                              void* d_out, int out_size) {
    const float* x    = (const float*)d_in[0];
    const float* wih  = (const float*)d_in[1];
    const float* whh  = (const float*)d_in[2];
    const float* bias = (const float*)d_in[3];
    float* out = (float*)d_out;

    void *p_x16, *p_wi16, *p_gx;
    cudaGetSymbolAddress(&p_x16,  g_x16);
    cudaGetSymbolAddress(&p_wi16, g_wi16);
    cudaGetSymbolAddress(&p_gx,   g_gx);

    cudaFuncSetAttribute(gru_persist_kernel,
                         cudaFuncAttributeMaxDynamicSharedMemorySize, SMEM_TOT);

    prep_all_kernel<<<16384, 1024>>>(x, whh, wih);

    mma_gemm16_kernel<<<dim3(24, M_ / 64), 128>>>(
        (const __half*)p_x16, (const __half*)p_wi16,
        (float*)p_gx, bias, F_);

    const long long seq_elems = (long long)B_ * S_ * HS_;
    float* lastdst = ((long long)out_size >= seq_elems + (long long)B_ * HS_)
                         ? out + seq_elems : nullptr;

    gru_persist_kernel<<<NBLK_P, NTHR, SMEM_TOT>>>(out, lastdst);
}